// round 9
// baseline (speedup 1.0000x reference)
#include <cuda_runtime.h>

// Accumulator we own (stays zeroed between replays: last block resets it).
__device__ float g_acc[6];
__device__ unsigned int g_cnt = 0;

__device__ __forceinline__ float ldcg(const float* p) {
    float v;
    asm volatile("ld.global.cg.f32 %0, [%1];" : "=f"(v) : "l"(p));
    return v;
}
__device__ __forceinline__ void stcg(float* p, float v) {
    asm volatile("st.global.cg.f32 [%0], %1;" :: "l"(p), "f"(v) : "memory");
}

// Single node: 64 blocks x 128 threads. Each block builds h[2048] in shared
// (redundant, ~7K FLOPs); each WARP computes one row of the 256x2048 GEMV
// (w3 row prefetched into regs at entry; launch_bounds(128,1) keeps it
// front-loaded -> proven 5.0us body). Per-block contributions to out[0..5]
// are combined in shared, folded into g_acc with 6 REDGs, and the LAST block
// (ticket) writes out = g_acc + b4 and resets scratch for the next replay.
__global__ void __launch_bounds__(128, 1) actor_main(
    const float* __restrict__ x,
    const float* __restrict__ conv_w, const float* __restrict__ conv_b,
    const float* __restrict__ w0, const float* __restrict__ b0,
    const float* __restrict__ w1, const float* __restrict__ b1,
    const float* __restrict__ w2, const float* __restrict__ b2,
    const float* __restrict__ w3, const float* __restrict__ b3,
    const float* __restrict__ w4, const float* __restrict__ b4,
    float* __restrict__ out)
{
    __shared__ __align__(16) float h[2048];
    __shared__ float s_con[4][6];
    __shared__ int s_last;

    const int c    = threadIdx.x;        // 0..127
    const int wid  = c >> 5;             // 0..3
    const int lane = c & 31;
    const int row  = (blockIdx.x << 2) + wid;   // this warp's GEMV row

    // ---- prefetch: full w3 row into regs (16 x LDG.128, MLP=16) ----
    const float4* __restrict__ w3r = reinterpret_cast<const float4*>(w3 + (size_t)row * 2048);
    float4 wv[16];
#pragma unroll
    for (int i = 0; i < 16; i++) wv[i] = w3r[lane + 32 * i];

    const float w4c = (lane < 6) ? w4[lane * 256 + row] : 0.0f;
    const float b3v = b3[row];
    const float b4v = (c < 6) ? b4[c] : 0.0f;

    // ---- inputs for h build (vectorized) ----
    const float4* __restrict__ x4p = reinterpret_cast<const float4*>(x);
    float4 xa = x4p[4];   // x[16..19]
    float4 xb = x4p[5];   // x[20..23]
    float4 xc = x4p[6];   // x[24..27]
    float4 xd = x4p[7];   // x[28..31]
    float4 xe = x4p[8];   // x[32..35]
    const float x36 = x[36], x37 = x[37];
    const float x07 = x[7];
    const float x17 = x[15];
    const float x47 = x[39];

    float x2r[8] = {xa.x, xa.y, xa.z, xa.w, xb.x, xb.y, xb.z, xb.w};
    float x3r[8] = {xc.x, xc.y, xc.z, xc.w, xd.x, xd.y, xd.z, xd.w};
    float x4r[6] = {xe.x, xe.y, xe.z, xe.w, x36, x37};

    float cw[4];
#pragma unroll
    for (int k = 0; k < 4; k++) cw[k] = conv_w[c * 4 + k];
    const float cb = conv_b[c];
    const float w0v = w0[c], b0v = b0[c];
    const float w1v = w1[c], b1v = b1[c];
    const float w2v = w2[c], b2v = b2[c];

    // ---- build h (thread c owns channel c) ----
    h[c]       = fmaxf(fmaf(w0v, x07, b0v), 0.0f);                 // s0 [0,128)
    h[128 + c] = fmaxf(fmaf(w1v, x17, b1v), 0.0f);                 // s1 [128,256)
#pragma unroll
    for (int t = 0; t < 5; t++) {                                   // s2,s3 conv T=5
        float a2 = cb, a3 = cb;
#pragma unroll
        for (int k = 0; k < 4; k++) {
            a2 = fmaf(cw[k], x2r[t + k], a2);
            a3 = fmaf(cw[k], x3r[t + k], a3);
        }
        h[256 + c * 5 + t] = fmaxf(a2, 0.0f);
        h[896 + c * 5 + t] = fmaxf(a3, 0.0f);
    }
#pragma unroll
    for (int t = 0; t < 3; t++) {                                   // s4 conv T=3
        float a4 = cb;
#pragma unroll
        for (int k = 0; k < 4; k++) a4 = fmaf(cw[k], x4r[t + k], a4);
        h[1536 + c * 3 + t] = fmaxf(a4, 0.0f);
    }
    h[1920 + c] = fmaf(w2v, x47, b2v);                              // s5 (no relu)

    __syncthreads();

    // ---- row dot: regs (w3) x shared (h), 64 elems/thread, 4 accumulators ----
    const float4* __restrict__ h4 = reinterpret_cast<const float4*>(h);
    float acc0 = 0.0f, acc1 = 0.0f, acc2 = 0.0f, acc3 = 0.0f;
#pragma unroll
    for (int i = 0; i < 16; i += 4) {
        float4 hv0 = h4[lane + 32 * i];
        float4 hv1 = h4[lane + 32 * (i + 1)];
        float4 hv2 = h4[lane + 32 * (i + 2)];
        float4 hv3 = h4[lane + 32 * (i + 3)];
        acc0 = fmaf(wv[i].x,     hv0.x, acc0); acc0 = fmaf(wv[i].y,     hv0.y, acc0);
        acc0 = fmaf(wv[i].z,     hv0.z, acc0); acc0 = fmaf(wv[i].w,     hv0.w, acc0);
        acc1 = fmaf(wv[i + 1].x, hv1.x, acc1); acc1 = fmaf(wv[i + 1].y, hv1.y, acc1);
        acc1 = fmaf(wv[i + 1].z, hv1.z, acc1); acc1 = fmaf(wv[i + 1].w, hv1.w, acc1);
        acc2 = fmaf(wv[i + 2].x, hv2.x, acc2); acc2 = fmaf(wv[i + 2].y, hv2.y, acc2);
        acc2 = fmaf(wv[i + 2].z, hv2.z, acc2); acc2 = fmaf(wv[i + 2].w, hv2.w, acc2);
        acc3 = fmaf(wv[i + 3].x, hv3.x, acc3); acc3 = fmaf(wv[i + 3].y, hv3.y, acc3);
        acc3 = fmaf(wv[i + 3].z, hv3.z, acc3); acc3 = fmaf(wv[i + 3].w, hv3.w, acc3);
    }
    float acc = (acc0 + acc1) + (acc2 + acc3);

#pragma unroll
    for (int o = 16; o > 0; o >>= 1) acc += __shfl_xor_sync(0xffffffffu, acc, o);
    // butterfly -> every lane holds the full row sum

    const float h3r = fmaxf(acc + b3v, 0.0f);

    // ---- per-block combine of the 4 warps' contributions ----
    if (lane < 6) s_con[wid][lane] = w4c * h3r;
    __syncthreads();

    if (c < 6) {
        float v = (s_con[0][c] + s_con[1][c]) + (s_con[2][c] + s_con[3][c]);
        asm volatile("red.global.add.f32 [%0], %1;"
                     :: "l"(g_acc + c), "f"(v) : "memory");
    }
    __threadfence();                     // order REDG before ticket
    if (c == 0) {
        unsigned int t = atomicAdd(&g_cnt, 1u);
        s_last = (t == 63u);
    }
    __syncthreads();
    if (!s_last) return;

    // ---- LAST block: finalize out and reset scratch for next replay ----
    __threadfence();                     // acquire other blocks' REDGs
    if (c < 6) {
        float v = ldcg(&g_acc[c]);
        out[c] = v + b4v;
        stcg(&g_acc[c], 0.0f);
    }
    if (c == 6) g_cnt = 0;
}

extern "C" void kernel_launch(void* const* d_in, const int* in_sizes, int n_in,
                              void* d_out, int out_size)
{
    const float* x      = (const float*)d_in[0];
    const float* conv_w = (const float*)d_in[1];
    const float* conv_b = (const float*)d_in[2];
    const float* w0     = (const float*)d_in[3];
    const float* b0     = (const float*)d_in[4];
    const float* w1     = (const float*)d_in[5];
    const float* b1     = (const float*)d_in[6];
    const float* w2     = (const float*)d_in[7];
    const float* b2     = (const float*)d_in[8];
    const float* w3     = (const float*)d_in[9];
    const float* b3     = (const float*)d_in[10];
    const float* w4     = (const float*)d_in[11];
    const float* b4     = (const float*)d_in[12];
    float* out = (float*)d_out;

    actor_main<<<64, 128>>>(x, conv_w, conv_b, w0, b0, w1, b1, w2, b2,
                            w3, b3, w4, b4, out);
}

// round 10
// speedup vs baseline: 1.3026x; 1.3026x over previous
#include <cuda_runtime.h>

// K0 (runs first, stream-ordered): out[j] = b4[j]. Gives REDG a clean base.
// Measured cost of this node: ~0.4us -- cheaper than any in-kernel rendezvous.
__global__ void actor_init(const float* __restrict__ b4, float* __restrict__ out)
{
    if (threadIdx.x < 6) out[threadIdx.x] = b4[threadIdx.x];
}

// K1: 64 blocks x 128 threads. Each block builds h[2048] in shared (redundant,
// ~7K FLOPs); each WARP computes one row of the 256x2048 GEMV (w3 row prefetched
// into regs at entry; launch_bounds(128,1) keeps the prefetch front-loaded --
// proven 5.0us body). The 4 warps' out-contributions are combined in shared,
// then ONE set of 6 fire-and-forget REDGs per block folds into out (384 total
// instead of 1536 -> 4x less L2 atomic drain before kernel retire).
__global__ void __launch_bounds__(128, 1) actor_main(
    const float* __restrict__ x,
    const float* __restrict__ conv_w, const float* __restrict__ conv_b,
    const float* __restrict__ w0, const float* __restrict__ b0,
    const float* __restrict__ w1, const float* __restrict__ b1,
    const float* __restrict__ w2, const float* __restrict__ b2,
    const float* __restrict__ w3, const float* __restrict__ b3,
    const float* __restrict__ w4,
    float* __restrict__ out)
{
    __shared__ __align__(16) float h[2048];
    __shared__ float s_con[4][6];

    const int c    = threadIdx.x;        // 0..127
    const int wid  = c >> 5;             // 0..3
    const int lane = c & 31;
    const int row  = (blockIdx.x << 2) + wid;   // this warp's GEMV row

    // ---- prefetch: full w3 row into regs (16 x LDG.128, MLP=16) ----
    const float4* __restrict__ w3r = reinterpret_cast<const float4*>(w3 + (size_t)row * 2048);
    float4 wv[16];
#pragma unroll
    for (int i = 0; i < 16; i++) wv[i] = w3r[lane + 32 * i];

    const float w4c = (lane < 6) ? w4[lane * 256 + row] : 0.0f;
    const float b3v = b3[row];

    // ---- inputs for h build (vectorized) ----
    const float4* __restrict__ x4p = reinterpret_cast<const float4*>(x);
    float4 xa = x4p[4];   // x[16..19]
    float4 xb = x4p[5];   // x[20..23]
    float4 xc = x4p[6];   // x[24..27]
    float4 xd = x4p[7];   // x[28..31]
    float4 xe = x4p[8];   // x[32..35]
    const float x36 = x[36], x37 = x[37];
    const float x07 = x[7];
    const float x17 = x[15];
    const float x47 = x[39];

    float x2r[8] = {xa.x, xa.y, xa.z, xa.w, xb.x, xb.y, xb.z, xb.w};
    float x3r[8] = {xc.x, xc.y, xc.z, xc.w, xd.x, xd.y, xd.z, xd.w};
    float x4r[6] = {xe.x, xe.y, xe.z, xe.w, x36, x37};

    float cw[4];
#pragma unroll
    for (int k = 0; k < 4; k++) cw[k] = conv_w[c * 4 + k];
    const float cb = conv_b[c];
    const float w0v = w0[c], b0v = b0[c];
    const float w1v = w1[c], b1v = b1[c];
    const float w2v = w2[c], b2v = b2[c];

    // ---- build h (thread c owns channel c) ----
    h[c]       = fmaxf(fmaf(w0v, x07, b0v), 0.0f);                 // s0 [0,128)
    h[128 + c] = fmaxf(fmaf(w1v, x17, b1v), 0.0f);                 // s1 [128,256)
#pragma unroll
    for (int t = 0; t < 5; t++) {                                   // s2,s3 conv T=5
        float a2 = cb, a3 = cb;
#pragma unroll
        for (int k = 0; k < 4; k++) {
            a2 = fmaf(cw[k], x2r[t + k], a2);
            a3 = fmaf(cw[k], x3r[t + k], a3);
        }
        h[256 + c * 5 + t] = fmaxf(a2, 0.0f);
        h[896 + c * 5 + t] = fmaxf(a3, 0.0f);
    }
#pragma unroll
    for (int t = 0; t < 3; t++) {                                   // s4 conv T=3
        float a4 = cb;
#pragma unroll
        for (int k = 0; k < 4; k++) a4 = fmaf(cw[k], x4r[t + k], a4);
        h[1536 + c * 3 + t] = fmaxf(a4, 0.0f);
    }
    h[1920 + c] = fmaf(w2v, x47, b2v);                              // s5 (no relu)

    __syncthreads();

    // ---- row dot: regs (w3) x shared (h), 64 elems/thread, 4 accumulators ----
    const float4* __restrict__ h4 = reinterpret_cast<const float4*>(h);
    float acc0 = 0.0f, acc1 = 0.0f, acc2 = 0.0f, acc3 = 0.0f;
#pragma unroll
    for (int i = 0; i < 16; i += 4) {
        float4 hv0 = h4[lane + 32 * i];
        float4 hv1 = h4[lane + 32 * (i + 1)];
        float4 hv2 = h4[lane + 32 * (i + 2)];
        float4 hv3 = h4[lane + 32 * (i + 3)];
        acc0 = fmaf(wv[i].x,     hv0.x, acc0); acc0 = fmaf(wv[i].y,     hv0.y, acc0);
        acc0 = fmaf(wv[i].z,     hv0.z, acc0); acc0 = fmaf(wv[i].w,     hv0.w, acc0);
        acc1 = fmaf(wv[i + 1].x, hv1.x, acc1); acc1 = fmaf(wv[i + 1].y, hv1.y, acc1);
        acc1 = fmaf(wv[i + 1].z, hv1.z, acc1); acc1 = fmaf(wv[i + 1].w, hv1.w, acc1);
        acc2 = fmaf(wv[i + 2].x, hv2.x, acc2); acc2 = fmaf(wv[i + 2].y, hv2.y, acc2);
        acc2 = fmaf(wv[i + 2].z, hv2.z, acc2); acc2 = fmaf(wv[i + 2].w, hv2.w, acc2);
        acc3 = fmaf(wv[i + 3].x, hv3.x, acc3); acc3 = fmaf(wv[i + 3].y, hv3.y, acc3);
        acc3 = fmaf(wv[i + 3].z, hv3.z, acc3); acc3 = fmaf(wv[i + 3].w, hv3.w, acc3);
    }
    float acc = (acc0 + acc1) + (acc2 + acc3);

#pragma unroll
    for (int o = 16; o > 0; o >>= 1) acc += __shfl_xor_sync(0xffffffffu, acc, o);
    // butterfly -> every lane holds the full row sum

    const float h3r = fmaxf(acc + b3v, 0.0f);

    // ---- combine the 4 warps' contributions in shared, 6 REDGs per block ----
    if (lane < 6) s_con[wid][lane] = w4c * h3r;
    __syncthreads();
    if (c < 6) {
        float v = (s_con[0][c] + s_con[1][c]) + (s_con[2][c] + s_con[3][c]);
        asm volatile("red.global.add.f32 [%0], %1;"
                     :: "l"(out + c), "f"(v) : "memory");
    }
}

extern "C" void kernel_launch(void* const* d_in, const int* in_sizes, int n_in,
                              void* d_out, int out_size)
{
    const float* x      = (const float*)d_in[0];
    const float* conv_w = (const float*)d_in[1];
    const float* conv_b = (const float*)d_in[2];
    const float* w0     = (const float*)d_in[3];
    const float* b0     = (const float*)d_in[4];
    const float* w1     = (const float*)d_in[5];
    const float* b1     = (const float*)d_in[6];
    const float* w2     = (const float*)d_in[7];
    const float* b2     = (const float*)d_in[8];
    const float* w3     = (const float*)d_in[9];
    const float* b3     = (const float*)d_in[10];
    const float* w4     = (const float*)d_in[11];
    const float* b4     = (const float*)d_in[12];
    float* out = (float*)d_out;

    actor_init<<<1, 32>>>(b4, out);
    actor_main<<<64, 128>>>(x, conv_w, conv_b, w0, b0, w1, b1, w2, b2,
                            w3, b3, w4, out);
}